// round 2
// baseline (speedup 1.0000x reference)
#include <cuda_runtime.h>
#include <math.h>

// ---------------- problem constants ----------------
#define BB   32
#define HH   56
#define WWI  56
#define CC   384
#define NHD  12
#define HDIM 32
#define WSZ  7
#define SSZ  3
#define NTOK 49          // tokens per window
#define NWIN 64          // windows per image
#define HIDN 1536        // mlp hidden
#define TTOT (BB*HH*WWI) // 100352 tokens
#define BWIN (BB*NWIN)   // 2048 windows
#define QKVC (3*CC)      // 1152

// ---------------- scratch (no allocs allowed) ----------------
__device__ float g_bufA[(size_t)TTOT * HIDN]; // qkv (1152 cols) then mlp-mid (1536 cols)
__device__ float g_bufB[(size_t)TTOT * CC];   // hw -> attn_out -> h2

// window-layout row r  <->  original-image token index (roll by +SS)
__device__ __forceinline__ int win2img(int r) {
    int bw = r / NTOK, n = r % NTOK;
    int b  = bw >> 6, wi = bw & 63;
    int wr = wi >> 3, wc = wi & 7;
    int nr = n / WSZ,  nc = n % WSZ;
    int hs = wr * WSZ + nr, ws = wc * WSZ + nc;
    int h = hs + SSZ; if (h >= HH)  h -= HH;
    int w = ws + SSZ; if (w >= WWI) w -= WWI;
    return (b * HH + h) * WWI + w;
}

// ---------------- LayerNorm (optionally gathered into window layout) ----------------
template<bool GATHER>
__global__ void ln_kernel(const float* __restrict__ in, const float* __restrict__ g,
                          const float* __restrict__ bta, float* __restrict__ out) {
    int r = blockIdx.x;
    int src = GATHER ? win2img(r) : r;
    const float* xr = in + (size_t)src * CC;
    int t = threadIdx.x; // 0..127
    float v0 = xr[t], v1 = xr[t + 128], v2 = xr[t + 256];
    float s = v0 + v1 + v2;
    float q = v0 * v0 + v1 * v1 + v2 * v2;
    #pragma unroll
    for (int o = 16; o; o >>= 1) {
        s += __shfl_xor_sync(0xffffffffu, s, o);
        q += __shfl_xor_sync(0xffffffffu, q, o);
    }
    __shared__ float ss[4], qq[4];
    int wid = t >> 5, lid = t & 31;
    if (!lid) { ss[wid] = s; qq[wid] = q; }
    __syncthreads();
    s = ss[0] + ss[1] + ss[2] + ss[3];
    q = qq[0] + qq[1] + qq[2] + qq[3];
    float mean = s * (1.0f / CC);
    float var  = q * (1.0f / CC) - mean * mean;
    float inv  = rsqrtf(var + 1e-5f);
    float* orow = out + (size_t)r * CC;
    orow[t]       = (v0 - mean) * inv * g[t]       + bta[t];
    orow[t + 128] = (v1 - mean) * inv * g[t + 128] + bta[t + 128];
    orow[t + 256] = (v2 - mean) * inv * g[t + 256] + bta[t + 256];
}

// ---------------- GEMM: C[M,N] = A[M,K] @ B[K,N] + epilogue ----------------
#define BM 128
#define BN 64
#define BKK 16
enum { EPI_BIAS = 0, EPI_GELU = 1, EPI_ADD = 2, EPI_PROJ = 3 };

template<int EPI>
__global__ __launch_bounds__(256)
void gemm_kernel(const float* __restrict__ A, const float* __restrict__ Bm,
                 const float* __restrict__ bias, float* __restrict__ Cout,
                 const float* __restrict__ resid, int M, int Nn, int K) {
    __shared__ float As[BKK][BM];
    __shared__ float Bs[BKK][BN];
    int tid = threadIdx.x;
    int tx = tid & 15, ty = tid >> 4;
    int rowBase = blockIdx.y * BM;
    int colBase = blockIdx.x * BN;
    float acc[8][4];
    #pragma unroll
    for (int i = 0; i < 8; i++)
        #pragma unroll
        for (int j = 0; j < 4; j++) acc[i][j] = 0.f;

    for (int k0 = 0; k0 < K; k0 += BKK) {
        #pragma unroll
        for (int l = 0; l < 2; l++) {
            int idx = (tid + l * 256) * 4;          // 0..2044
            int m = idx >> 4, kk = idx & 15;
            float4 av = *(const float4*)(A + (size_t)(rowBase + m) * K + k0 + kk);
            As[kk    ][m] = av.x;
            As[kk + 1][m] = av.y;
            As[kk + 2][m] = av.z;
            As[kk + 3][m] = av.w;
        }
        {
            int idx = tid * 4;                      // 0..1020
            int kk = idx >> 6, n = idx & 63;
            float4 bv = *(const float4*)(Bm + (size_t)(k0 + kk) * Nn + colBase + n);
            *(float4*)&Bs[kk][n] = bv;
        }
        __syncthreads();
        #pragma unroll
        for (int kk = 0; kk < BKK; kk++) {
            float ar[8], br[4];
            #pragma unroll
            for (int i = 0; i < 8; i++) ar[i] = As[kk][ty * 8 + i];
            #pragma unroll
            for (int j = 0; j < 4; j++) br[j] = Bs[kk][tx * 4 + j];
            #pragma unroll
            for (int i = 0; i < 8; i++)
                #pragma unroll
                for (int j = 0; j < 4; j++) acc[i][j] += ar[i] * br[j];
        }
        __syncthreads();
    }

    int c0 = colBase + tx * 4;
    float4 bvec = *(const float4*)(bias + c0);
    #pragma unroll
    for (int i = 0; i < 8; i++) {
        int r = rowBase + ty * 8 + i;
        int dstrow = (EPI == EPI_PROJ) ? win2img(r) : r;
        float4 v;
        v.x = acc[i][0] + bvec.x;
        v.y = acc[i][1] + bvec.y;
        v.z = acc[i][2] + bvec.z;
        v.w = acc[i][3] + bvec.w;
        if (EPI == EPI_GELU) {
            v.x = 0.5f * v.x * (1.f + erff(v.x * 0.70710678118654752f));
            v.y = 0.5f * v.y * (1.f + erff(v.y * 0.70710678118654752f));
            v.z = 0.5f * v.z * (1.f + erff(v.z * 0.70710678118654752f));
            v.w = 0.5f * v.w * (1.f + erff(v.w * 0.70710678118654752f));
        }
        if (EPI == EPI_ADD || EPI == EPI_PROJ) {
            float4 rv = *(const float4*)(resid + (size_t)dstrow * Nn + c0);
            v.x += rv.x; v.y += rv.y; v.z += rv.z; v.w += rv.w;
        }
        *(float4*)(Cout + (size_t)dstrow * Nn + c0) = v;
    }
}

// ---------------- windowed attention: one block per (window, head) ----------------
__global__ __launch_bounds__(256)
void attn_kernel(const float* __restrict__ qkv, const float* __restrict__ rpb,
                 float* __restrict__ out) {
    __shared__ float q[NTOK * HDIM], k[NTOK * HDIM], v[NTOK * HDIM];
    __shared__ float sc[NTOK * 50];
    int bw = blockIdx.y;   // 0..2047
    int hid = blockIdx.x;  // 0..11
    int tid = threadIdx.x;
    const float scale = 0.17677669529663687f; // 32^-0.5

    for (int idx = tid; idx < NTOK * HDIM; idx += 256) {
        int n = idx >> 5, d = idx & 31;
        size_t base = (size_t)(bw * NTOK + n) * QKVC + hid * HDIM + d;
        q[idx] = qkv[base] * scale;
        k[idx] = qkv[base + CC];
        v[idx] = qkv[base + 2 * CC];
    }
    __syncthreads();

    int wi = bw & 63;
    int wr = wi >> 3, wc = wi & 7;
    for (int p = tid; p < NTOK * NTOK; p += 256) {
        int i = p / NTOK, j = p - i * NTOK;
        float s = 0.f;
        #pragma unroll
        for (int d = 0; d < HDIM; d++) s += q[i * HDIM + d] * k[j * HDIM + d];
        int ri = i / 7, ci = i - ri * 7;
        int rj = j / 7, cj = j - rj * 7;
        // relative position bias
        int bidx = (ri - rj + 6) * 13 + (ci - cj + 6);
        s += rpb[bidx * NHD + hid];
        // shifted-window mask: region id from rolled-image coords
        int hi = wr * 7 + ri, wci = wc * 7 + ci;
        int hj = wr * 7 + rj, wcj = wc * 7 + cj;
        int regi = (hi < 49 ? 0 : (hi < 53 ? 1 : 2)) * 3 + (wci < 49 ? 0 : (wci < 53 ? 1 : 2));
        int regj = (hj < 49 ? 0 : (hj < 53 ? 1 : 2)) * 3 + (wcj < 49 ? 0 : (wcj < 53 ? 1 : 2));
        if (regi != regj) s -= 100.f;
        sc[i * 50 + j] = s;
    }
    __syncthreads();

    if (tid < NTOK) {
        float mx = -1e30f;
        #pragma unroll 7
        for (int j = 0; j < NTOK; j++) mx = fmaxf(mx, sc[tid * 50 + j]);
        float sum = 0.f;
        #pragma unroll 7
        for (int j = 0; j < NTOK; j++) {
            float e = __expf(sc[tid * 50 + j] - mx);
            sc[tid * 50 + j] = e;
            sum += e;
        }
        float inv = 1.f / sum;
        #pragma unroll 7
        for (int j = 0; j < NTOK; j++) sc[tid * 50 + j] *= inv;
    }
    __syncthreads();

    for (int idx = tid; idx < NTOK * HDIM; idx += 256) {
        int i = idx >> 5, d = idx & 31;
        float s = 0.f;
        #pragma unroll 7
        for (int j = 0; j < NTOK; j++) s += sc[i * 50 + j] * v[j * HDIM + d];
        out[(size_t)(bw * NTOK + i) * CC + hid * HDIM + d] = s;
    }
}

// ---------------- launch ----------------
extern "C" void kernel_launch(void* const* d_in, const int* in_sizes, int n_in,
                              void* d_out, int out_size) {
    const float* x      = (const float*)d_in[0];
    const float* g1     = (const float*)d_in[1];
    const float* b1     = (const float*)d_in[2];
    const float* w_qkv  = (const float*)d_in[3];
    const float* b_qkv  = (const float*)d_in[4];
    const float* w_proj = (const float*)d_in[5];
    const float* b_proj = (const float*)d_in[6];
    const float* rpb    = (const float*)d_in[7];
    const float* g2     = (const float*)d_in[8];
    const float* b2     = (const float*)d_in[9];
    const float* w1     = (const float*)d_in[10];
    const float* bm1    = (const float*)d_in[11];
    const float* w2     = (const float*)d_in[12];
    const float* bm2    = (const float*)d_in[13];
    float* out = (float*)d_out;

    float *bufA = nullptr, *bufB = nullptr;
    cudaGetSymbolAddress((void**)&bufA, g_bufA);
    cudaGetSymbolAddress((void**)&bufB, g_bufB);

    // 1) LN1 + roll(-3,-3) + window partition  -> bufB [100352,384]
    ln_kernel<true><<<TTOT, 128>>>(x, g1, b1, bufB);
    // 2) QKV GEMM -> bufA [100352,1152]
    gemm_kernel<EPI_BIAS><<<dim3(QKVC / BN, TTOT / BM), 256>>>(
        bufB, w_qkv, b_qkv, bufA, nullptr, TTOT, QKVC, CC);
    // 3) windowed attention -> bufB [100352,384]
    attn_kernel<<<dim3(NHD, BWIN), 256>>>(bufA, rpb, bufB);
    // 4) proj + window reverse + roll(+3,+3) + residual(x) -> out
    gemm_kernel<EPI_PROJ><<<dim3(CC / BN, TTOT / BM), 256>>>(
        bufB, w_proj, b_proj, out, x, TTOT, CC, CC);
    // 5) LN2 -> bufB
    ln_kernel<false><<<TTOT, 128>>>(out, g2, b2, bufB);
    // 6) FC1 + exact GELU -> bufA [100352,1536]
    gemm_kernel<EPI_GELU><<<dim3(HIDN / BN, TTOT / BM), 256>>>(
        bufB, w1, bm1, bufA, nullptr, TTOT, HIDN, CC);
    // 7) FC2 + residual(out) -> out
    gemm_kernel<EPI_ADD><<<dim3(CC / BN, TTOT / BM), 256>>>(
        bufA, w2, bm2, out, out, TTOT, CC, HIDN);
}

// round 3
// speedup vs baseline: 1.9474x; 1.9474x over previous
#include <cuda_runtime.h>
#include <math.h>
#include <stdint.h>

// ---------------- problem constants ----------------
#define BB   32
#define HH   56
#define WWI  56
#define CC   384
#define NHD  12
#define HDIM 32
#define WSZ  7
#define SSZ  3
#define NTOK 49
#define NWIN 64
#define HIDN 1536
#define TTOT (BB*HH*WWI) // 100352
#define BWIN (BB*NWIN)   // 2048
#define QKVC (3*CC)      // 1152

// ---------------- scratch ----------------
__device__ float g_bufA[(size_t)TTOT * HIDN];
__device__ float g_bufB[(size_t)TTOT * CC];

__device__ __forceinline__ int win2img(int r) {
    int bw = r / NTOK, n = r % NTOK;
    int b  = bw >> 6, wi = bw & 63;
    int wr = wi >> 3, wc = wi & 7;
    int nr = n / WSZ,  nc = n % WSZ;
    int hs = wr * WSZ + nr, ws = wc * WSZ + nc;
    int h = hs + SSZ; if (h >= HH)  h -= HH;
    int w = ws + SSZ; if (w >= WWI) w -= WWI;
    return (b * HH + h) * WWI + w;
}

// ---------------- LayerNorm ----------------
template<bool GATHER>
__global__ void ln_kernel(const float* __restrict__ in, const float* __restrict__ g,
                          const float* __restrict__ bta, float* __restrict__ out) {
    int r = blockIdx.x;
    int src = GATHER ? win2img(r) : r;
    const float* xr = in + (size_t)src * CC;
    int t = threadIdx.x;
    float v0 = xr[t], v1 = xr[t + 128], v2 = xr[t + 256];
    float s = v0 + v1 + v2;
    float q = v0 * v0 + v1 * v1 + v2 * v2;
    #pragma unroll
    for (int o = 16; o; o >>= 1) {
        s += __shfl_xor_sync(0xffffffffu, s, o);
        q += __shfl_xor_sync(0xffffffffu, q, o);
    }
    __shared__ float ss[4], qq[4];
    int wid = t >> 5, lid = t & 31;
    if (!lid) { ss[wid] = s; qq[wid] = q; }
    __syncthreads();
    s = ss[0] + ss[1] + ss[2] + ss[3];
    q = qq[0] + qq[1] + qq[2] + qq[3];
    float mean = s * (1.0f / CC);
    float var  = q * (1.0f / CC) - mean * mean;
    float inv  = rsqrtf(var + 1e-5f);
    float* orow = out + (size_t)r * CC;
    orow[t]       = (v0 - mean) * inv * g[t]       + bta[t];
    orow[t + 128] = (v1 - mean) * inv * g[t + 128] + bta[t + 128];
    orow[t + 256] = (v2 - mean) * inv * g[t + 256] + bta[t + 256];
}

// ---------------- tf32 tensor-core GEMM ----------------
enum { EPI_BIAS = 0, EPI_GELU = 1, EPI_ADD = 2, EPI_PROJ = 3 };

__device__ __forceinline__ uint32_t f2tf(float f) {
    uint32_t u;
    asm("cvt.rna.tf32.f32 %0, %1;" : "=r"(u) : "f"(f));
    return u;
}

__device__ __forceinline__ void mma_tf32(float* c, const uint32_t* a, const uint32_t* b) {
    asm volatile(
        "mma.sync.aligned.m16n8k8.row.col.f32.tf32.tf32.f32 "
        "{%0,%1,%2,%3}, {%4,%5,%6,%7}, {%8,%9}, {%0,%1,%2,%3};"
        : "+f"(c[0]), "+f"(c[1]), "+f"(c[2]), "+f"(c[3])
        : "r"(a[0]), "r"(a[1]), "r"(a[2]), "r"(a[3]), "r"(b[0]), "r"(b[1]));
}

// CTA tile 128x128xBK16, 8 warps (4x2), warp tile 32x64.
template<int EPI>
__global__ __launch_bounds__(256)
void gemm_tc(const float* __restrict__ A, const float* __restrict__ Bm,
             const float* __restrict__ bias, float* __restrict__ Cout,
             const float* __restrict__ resid, int M, int Nn, int K) {
    __shared__ uint32_t As[2][16][128];
    __shared__ uint32_t Bs[2][16][128];

    int tid = threadIdx.x;
    int lane = tid & 31, warp = tid >> 5;
    int g = lane >> 2, t = lane & 3;
    int wm = (warp >> 1) * 32, wn = (warp & 1) * 64;
    int rowBase = blockIdx.y * 128, colBase = blockIdx.x * 128;

    // gmem load geometry (2 float4 of A, 2 float4 of B per thread per iter)
    int am[2], akq[2], bk[2], bn[2];
    const float* aptr[2];
    const float* bptr[2];
    #pragma unroll
    for (int l = 0; l < 2; l++) {
        int f = tid + l * 256;
        am[l]  = f >> 2;          // 0..127
        akq[l] = f & 3;           // k-quad
        aptr[l] = A + (size_t)(rowBase + am[l]) * K + akq[l] * 4;
        bk[l] = f >> 5;           // 0..15
        bn[l] = (f & 31) * 4;     // 0..124
        bptr[l] = Bm + (size_t)bk[l] * Nn + colBase + bn[l];
    }

    float acc[2][8][4];
    #pragma unroll
    for (int mt = 0; mt < 2; mt++)
        #pragma unroll
        for (int nt = 0; nt < 8; nt++)
            #pragma unroll
            for (int j = 0; j < 4; j++) acc[mt][nt][j] = 0.f;

    int kIters = K >> 4;
    float4 fa[2], fb[2];

    // preload iter 0
    #pragma unroll
    for (int l = 0; l < 2; l++) {
        fa[l] = *(const float4*)(aptr[l]);
        fb[l] = *(const float4*)(bptr[l]);
    }
    // store iter 0 into buf 0
    #pragma unroll
    for (int l = 0; l < 2; l++) {
        float av[4] = {fa[l].x, fa[l].y, fa[l].z, fa[l].w};
        #pragma unroll
        for (int j = 0; j < 4; j++) {
            int sw = (((j ^ akq[l]) & 3) << 3);
            As[0][akq[l] * 4 + j][am[l] ^ sw] = f2tf(av[j]);
        }
        int sw = (((bk[l] & 3) ^ ((bk[l] >> 2) & 3)) << 3);
        uint4 bq = make_uint4(f2tf(fb[l].x), f2tf(fb[l].y), f2tf(fb[l].z), f2tf(fb[l].w));
        *(uint4*)&Bs[0][bk[l]][bn[l] ^ sw] = bq;
    }
    __syncthreads();

    int buf = 0;
    for (int it = 0; it < kIters; ++it) {
        bool more = (it + 1 < kIters);
        if (more) {
            size_t koff = (size_t)(it + 1) * 16;
            #pragma unroll
            for (int l = 0; l < 2; l++) {
                fa[l] = *(const float4*)(aptr[l] + koff);
                fb[l] = *(const float4*)(bptr[l] + koff * Nn);
            }
        }
        // compute from buf
        #pragma unroll
        for (int ks = 0; ks < 2; ks++) {
            int kb = ks * 8;
            int c1 = kb >> 2;                    // 0 or 2
            int s1 = ((t ^ c1) & 3) << 3;
            int s2 = ((t ^ (c1 + 1)) & 3) << 3;
            uint32_t af[2][4], bf[8][2];
            #pragma unroll
            for (int mt = 0; mt < 2; mt++) {
                int m0 = wm + mt * 16;
                af[mt][0] = As[buf][kb + t    ][(m0 + g)     ^ s1];
                af[mt][1] = As[buf][kb + t    ][(m0 + 8 + g) ^ s1];
                af[mt][2] = As[buf][kb + t + 4][(m0 + g)     ^ s2];
                af[mt][3] = As[buf][kb + t + 4][(m0 + 8 + g) ^ s2];
            }
            #pragma unroll
            for (int nt = 0; nt < 8; nt++) {
                int n0 = wn + nt * 8 + g;
                bf[nt][0] = Bs[buf][kb + t    ][n0 ^ s1];
                bf[nt][1] = Bs[buf][kb + t + 4][n0 ^ s2];
            }
            #pragma unroll
            for (int mt = 0; mt < 2; mt++)
                #pragma unroll
                for (int nt = 0; nt < 8; nt++)
                    mma_tf32(acc[mt][nt], af[mt], bf[nt]);
        }
        if (more) {
            int nb = buf ^ 1;
            #pragma unroll
            for (int l = 0; l < 2; l++) {
                float av[4] = {fa[l].x, fa[l].y, fa[l].z, fa[l].w};
                #pragma unroll
                for (int j = 0; j < 4; j++) {
                    int sw = (((j ^ akq[l]) & 3) << 3);
                    As[nb][akq[l] * 4 + j][am[l] ^ sw] = f2tf(av[j]);
                }
                int sw = (((bk[l] & 3) ^ ((bk[l] >> 2) & 3)) << 3);
                uint4 bq = make_uint4(f2tf(fb[l].x), f2tf(fb[l].y), f2tf(fb[l].z), f2tf(fb[l].w));
                *(uint4*)&Bs[nb][bk[l]][bn[l] ^ sw] = bq;
            }
        }
        __syncthreads();
        buf ^= 1;
    }

    // epilogue
    #pragma unroll
    for (int mt = 0; mt < 2; mt++) {
        #pragma unroll
        for (int p = 0; p < 2; p++) {
            int r = rowBase + wm + mt * 16 + g + p * 8;
            int dstrow = (EPI == EPI_PROJ) ? win2img(r) : r;
            #pragma unroll
            for (int nt = 0; nt < 8; nt++) {
                int col = colBase + wn + nt * 8 + t * 2;
                float2 bv = *(const float2*)(bias + col);
                float vx = acc[mt][nt][p * 2 + 0] + bv.x;
                float vy = acc[mt][nt][p * 2 + 1] + bv.y;
                if (EPI == EPI_GELU) {
                    vx = 0.5f * vx * (1.f + erff(vx * 0.70710678118654752f));
                    vy = 0.5f * vy * (1.f + erff(vy * 0.70710678118654752f));
                }
                if (EPI == EPI_ADD || EPI == EPI_PROJ) {
                    float2 rv = *(const float2*)(resid + (size_t)dstrow * Nn + col);
                    vx += rv.x; vy += rv.y;
                }
                float2 ov; ov.x = vx; ov.y = vy;
                *(float2*)(Cout + (size_t)dstrow * Nn + col) = ov;
            }
        }
    }
}

// ---------------- windowed attention ----------------
__global__ __launch_bounds__(256)
void attn_kernel(const float* __restrict__ qkv, const float* __restrict__ rpb,
                 float* __restrict__ out) {
    __shared__ float q[NTOK * HDIM], k[NTOK * HDIM], v[NTOK * HDIM];
    __shared__ float sc[NTOK * 50];
    int bw = blockIdx.y;
    int hid = blockIdx.x;
    int tid = threadIdx.x;
    const float scale = 0.17677669529663687f;

    for (int idx = tid; idx < NTOK * HDIM; idx += 256) {
        int n = idx >> 5, d = idx & 31;
        size_t base = (size_t)(bw * NTOK + n) * QKVC + hid * HDIM + d;
        q[idx] = qkv[base] * scale;
        k[idx] = qkv[base + CC];
        v[idx] = qkv[base + 2 * CC];
    }
    __syncthreads();

    int wi = bw & 63;
    int wr = wi >> 3, wc = wi & 7;
    for (int p = tid; p < NTOK * NTOK; p += 256) {
        int i = p / NTOK, j = p - i * NTOK;
        float s = 0.f;
        #pragma unroll
        for (int d = 0; d < HDIM; d++) s += q[i * HDIM + d] * k[j * HDIM + d];
        int ri = i / 7, ci = i - ri * 7;
        int rj = j / 7, cj = j - rj * 7;
        int bidx = (ri - rj + 6) * 13 + (ci - cj + 6);
        s += rpb[bidx * NHD + hid];
        int hi = wr * 7 + ri, wci = wc * 7 + ci;
        int hj = wr * 7 + rj, wcj = wc * 7 + cj;
        int regi = (hi < 49 ? 0 : (hi < 53 ? 1 : 2)) * 3 + (wci < 49 ? 0 : (wci < 53 ? 1 : 2));
        int regj = (hj < 49 ? 0 : (hj < 53 ? 1 : 2)) * 3 + (wcj < 49 ? 0 : (wcj < 53 ? 1 : 2));
        if (regi != regj) s -= 100.f;
        sc[i * 50 + j] = s;
    }
    __syncthreads();

    if (tid < NTOK) {
        float mx = -1e30f;
        #pragma unroll 7
        for (int j = 0; j < NTOK; j++) mx = fmaxf(mx, sc[tid * 50 + j]);
        float sum = 0.f;
        #pragma unroll 7
        for (int j = 0; j < NTOK; j++) {
            float e = __expf(sc[tid * 50 + j] - mx);
            sc[tid * 50 + j] = e;
            sum += e;
        }
        float inv = 1.f / sum;
        #pragma unroll 7
        for (int j = 0; j < NTOK; j++) sc[tid * 50 + j] *= inv;
    }
    __syncthreads();

    for (int idx = tid; idx < NTOK * HDIM; idx += 256) {
        int i = idx >> 5, d = idx & 31;
        float s = 0.f;
        #pragma unroll 7
        for (int j = 0; j < NTOK; j++) s += sc[i * 50 + j] * v[j * HDIM + d];
        out[(size_t)(bw * NTOK + i) * CC + hid * HDIM + d] = s;
    }
}

// ---------------- launch ----------------
extern "C" void kernel_launch(void* const* d_in, const int* in_sizes, int n_in,
                              void* d_out, int out_size) {
    const float* x      = (const float*)d_in[0];
    const float* g1     = (const float*)d_in[1];
    const float* b1     = (const float*)d_in[2];
    const float* w_qkv  = (const float*)d_in[3];
    const float* b_qkv  = (const float*)d_in[4];
    const float* w_proj = (const float*)d_in[5];
    const float* b_proj = (const float*)d_in[6];
    const float* rpb    = (const float*)d_in[7];
    const float* g2     = (const float*)d_in[8];
    const float* b2     = (const float*)d_in[9];
    const float* w1     = (const float*)d_in[10];
    const float* bm1    = (const float*)d_in[11];
    const float* w2     = (const float*)d_in[12];
    const float* bm2    = (const float*)d_in[13];
    float* out = (float*)d_out;

    float *bufA = nullptr, *bufB = nullptr;
    cudaGetSymbolAddress((void**)&bufA, g_bufA);
    cudaGetSymbolAddress((void**)&bufB, g_bufB);

    // 1) LN1 + roll + window partition -> bufB
    ln_kernel<true><<<TTOT, 128>>>(x, g1, b1, bufB);
    // 2) QKV GEMM -> bufA
    gemm_tc<EPI_BIAS><<<dim3(QKVC / 128, TTOT / 128), 256>>>(
        bufB, w_qkv, b_qkv, bufA, nullptr, TTOT, QKVC, CC);
    // 3) windowed attention -> bufB
    attn_kernel<<<dim3(NHD, BWIN), 256>>>(bufA, rpb, bufB);
    // 4) proj + window reverse + roll + residual -> out
    gemm_tc<EPI_PROJ><<<dim3(CC / 128, TTOT / 128), 256>>>(
        bufB, w_proj, b_proj, out, x, TTOT, CC, CC);
    // 5) LN2 -> bufB
    ln_kernel<false><<<TTOT, 128>>>(out, g2, b2, bufB);
    // 6) FC1 + GELU -> bufA
    gemm_tc<EPI_GELU><<<dim3(HIDN / 128, TTOT / 128), 256>>>(
        bufB, w1, bm1, bufA, nullptr, TTOT, HIDN, CC);
    // 7) FC2 + residual -> out
    gemm_tc<EPI_ADD><<<dim3(CC / 128, TTOT / 128), 256>>>(
        bufA, w2, bm2, out, out, TTOT, CC, HIDN);
}

// round 4
// speedup vs baseline: 2.8107x; 1.4433x over previous
#include <cuda_runtime.h>
#include <math.h>
#include <stdint.h>

// ---------------- problem constants ----------------
#define BB   32
#define HH   56
#define WWI  56
#define CC   384
#define NHD  12
#define HDIM 32
#define WSZ  7
#define SSZ  3
#define NTOK 49
#define NWIN 64
#define HIDN 1536
#define TTOT (BB*HH*WWI) // 100352
#define BWIN (BB*NWIN)   // 2048
#define QKVC (3*CC)      // 1152

// ---------------- scratch ----------------
__device__ float g_bufA[(size_t)TTOT * HIDN];
__device__ float g_bufB[(size_t)TTOT * CC];

__device__ __forceinline__ int win2img(int r) {
    int bw = r / NTOK, n = r % NTOK;
    int b  = bw >> 6, wi = bw & 63;
    int wr = wi >> 3, wc = wi & 7;
    int nr = n / WSZ,  nc = n % WSZ;
    int hs = wr * WSZ + nr, ws = wc * WSZ + nc;
    int h = hs + SSZ; if (h >= HH)  h -= HH;
    int w = ws + SSZ; if (w >= WWI) w -= WWI;
    return (b * HH + h) * WWI + w;
}

// ---------------- LayerNorm ----------------
template<bool GATHER>
__global__ void ln_kernel(const float* __restrict__ in, const float* __restrict__ g,
                          const float* __restrict__ bta, float* __restrict__ out) {
    int r = blockIdx.x;
    int src = GATHER ? win2img(r) : r;
    const float* xr = in + (size_t)src * CC;
    int t = threadIdx.x;
    float v0 = xr[t], v1 = xr[t + 128], v2 = xr[t + 256];
    float s = v0 + v1 + v2;
    float q = v0 * v0 + v1 * v1 + v2 * v2;
    #pragma unroll
    for (int o = 16; o; o >>= 1) {
        s += __shfl_xor_sync(0xffffffffu, s, o);
        q += __shfl_xor_sync(0xffffffffu, q, o);
    }
    __shared__ float ss[4], qq[4];
    int wid = t >> 5, lid = t & 31;
    if (!lid) { ss[wid] = s; qq[wid] = q; }
    __syncthreads();
    s = ss[0] + ss[1] + ss[2] + ss[3];
    q = qq[0] + qq[1] + qq[2] + qq[3];
    float mean = s * (1.0f / CC);
    float var  = q * (1.0f / CC) - mean * mean;
    float inv  = rsqrtf(var + 1e-5f);
    float* orow = out + (size_t)r * CC;
    orow[t]       = (v0 - mean) * inv * g[t]       + bta[t];
    orow[t + 128] = (v1 - mean) * inv * g[t + 128] + bta[t + 128];
    orow[t + 256] = (v2 - mean) * inv * g[t + 256] + bta[t + 256];
}

// ---------------- tf32 tensor-core GEMM (cp.async, 3-stage) ----------------
enum { EPI_BIAS = 0, EPI_GELU = 1, EPI_ADD = 2, EPI_PROJ = 3 };

#define STAGES 3
#define AS_STRIDE 20            // 16 + 4 pad : banks 20g+t distinct (g<8,t<8)
#define BS_STRIDE 132           // 128 + 4 pad: banks 4t+g distinct (t<8,g<8)
#define AS_WORDS (128 * AS_STRIDE)   // 2560
#define BS_WORDS (16 * BS_STRIDE)    // 2112
#define SMEM_BYTES ((STAGES * (AS_WORDS + BS_WORDS)) * 4)  // 56064

__device__ __forceinline__ void cp_async16(uint32_t saddr, const void* gptr) {
    asm volatile("cp.async.cg.shared.global [%0], [%1], 16;" :: "r"(saddr), "l"(gptr));
}
__device__ __forceinline__ void cp_commit() {
    asm volatile("cp.async.commit_group;");
}
__device__ __forceinline__ void cp_wait1() {
    asm volatile("cp.async.wait_group 1;");
}

__device__ __forceinline__ void mma_tf32(float* c, const uint32_t* a, const uint32_t* b) {
    asm volatile(
        "mma.sync.aligned.m16n8k8.row.col.f32.tf32.tf32.f32 "
        "{%0,%1,%2,%3}, {%4,%5,%6,%7}, {%8,%9}, {%0,%1,%2,%3};"
        : "+f"(c[0]), "+f"(c[1]), "+f"(c[2]), "+f"(c[3])
        : "r"(a[0]), "r"(a[1]), "r"(a[2]), "r"(a[3]), "r"(b[0]), "r"(b[1]));
}

// CTA 128x128xK16, 8 warps (4x2 grid), warp tile 32x64.
template<int EPI>
__global__ __launch_bounds__(256)
void gemm_tc(const float* __restrict__ A, const float* __restrict__ Bm,
             const float* __restrict__ bias, float* __restrict__ Cout,
             const float* __restrict__ resid, int M, int Nn, int K) {
    extern __shared__ float smem[];
    float* As = smem;                       // [STAGES][128][AS_STRIDE]
    float* Bs = smem + STAGES * AS_WORDS;   // [STAGES][16][BS_STRIDE]

    int tid = threadIdx.x;
    int lane = tid & 31, warp = tid >> 5;
    int g = lane >> 2, t = lane & 3;
    int wm = (warp >> 1) * 32, wn = (warp & 1) * 64;
    int rowBase = blockIdx.y * 128, colBase = blockIdx.x * 128;

    // cp.async geometry: 2 A-float4 + 2 B-float4 per thread per k-iter
    int am[2], akq[2], bk[2], bn[2];
    const float* aptr[2];
    const float* bptr[2];
    uint32_t a_s[2], b_s[2];
    #pragma unroll
    for (int l = 0; l < 2; l++) {
        int f = tid + l * 256;
        am[l]  = f >> 2;
        akq[l] = f & 3;
        aptr[l] = A + (size_t)(rowBase + am[l]) * K + akq[l] * 4;
        bk[l] = f >> 5;
        bn[l] = (f & 31) * 4;
        bptr[l] = Bm + (size_t)bk[l] * Nn + colBase + bn[l];
        a_s[l] = (uint32_t)__cvta_generic_to_shared(As + am[l] * AS_STRIDE + akq[l] * 4);
        b_s[l] = (uint32_t)__cvta_generic_to_shared(Bs + bk[l] * BS_STRIDE + bn[l]);
    }

    float acc[2][8][4];
    #pragma unroll
    for (int mt = 0; mt < 2; mt++)
        #pragma unroll
        for (int nt = 0; nt < 8; nt++)
            #pragma unroll
            for (int j = 0; j < 4; j++) acc[mt][nt][j] = 0.f;

    int kIters = K >> 4;

    // prologue: stages 0,1
    #pragma unroll
    for (int s = 0; s < STAGES - 1; s++) {
        size_t koff = (size_t)s * 16;
        #pragma unroll
        for (int l = 0; l < 2; l++) {
            cp_async16(a_s[l] + s * AS_WORDS * 4, aptr[l] + koff);
            cp_async16(b_s[l] + s * BS_WORDS * 4, bptr[l] + koff * Nn);
        }
        cp_commit();
    }

    int stage = 0;
    for (int it = 0; it < kIters; ++it) {
        cp_wait1();
        __syncthreads();

        const float* as = As + stage * AS_WORDS + (wm + g) * AS_STRIDE + t;
        const float* bs = Bs + stage * BS_WORDS + t * BS_STRIDE + wn + g;

        #pragma unroll
        for (int ks = 0; ks < 2; ks++) {
            int kb = ks * 8;
            uint32_t af[2][4], bf[8][2];
            #pragma unroll
            for (int mt = 0; mt < 2; mt++) {
                af[mt][0] = __float_as_uint(as[(mt * 16    ) * AS_STRIDE + kb    ]);
                af[mt][1] = __float_as_uint(as[(mt * 16 + 8) * AS_STRIDE + kb    ]);
                af[mt][2] = __float_as_uint(as[(mt * 16    ) * AS_STRIDE + kb + 4]);
                af[mt][3] = __float_as_uint(as[(mt * 16 + 8) * AS_STRIDE + kb + 4]);
            }
            #pragma unroll
            for (int nt = 0; nt < 8; nt++) {
                bf[nt][0] = __float_as_uint(bs[(kb    ) * BS_STRIDE + nt * 8]);
                bf[nt][1] = __float_as_uint(bs[(kb + 4) * BS_STRIDE + nt * 8]);
            }
            #pragma unroll
            for (int mt = 0; mt < 2; mt++)
                #pragma unroll
                for (int nt = 0; nt < 8; nt++)
                    mma_tf32(acc[mt][nt], af[mt], bf[nt]);
        }

        int nk = it + STAGES - 1;
        if (nk < kIters) {
            int ns = stage;  // (stage + STAGES - 1) % STAGES == stage - 1... compute explicitly
            ns = stage + (STAGES - 1); if (ns >= STAGES) ns -= STAGES;
            size_t koff = (size_t)nk * 16;
            #pragma unroll
            for (int l = 0; l < 2; l++) {
                cp_async16(a_s[l] + ns * AS_WORDS * 4, aptr[l] + koff);
                cp_async16(b_s[l] + ns * BS_WORDS * 4, bptr[l] + koff * Nn);
            }
        }
        cp_commit();

        stage = stage + 1; if (stage == STAGES) stage = 0;
    }

    // epilogue
    #pragma unroll
    for (int mt = 0; mt < 2; mt++) {
        #pragma unroll
        for (int p = 0; p < 2; p++) {
            int r = rowBase + wm + mt * 16 + g + p * 8;
            int dstrow = (EPI == EPI_PROJ) ? win2img(r) : r;
            #pragma unroll
            for (int nt = 0; nt < 8; nt++) {
                int col = colBase + wn + nt * 8 + t * 2;
                float2 bv = *(const float2*)(bias + col);
                float vx = acc[mt][nt][p * 2 + 0] + bv.x;
                float vy = acc[mt][nt][p * 2 + 1] + bv.y;
                if (EPI == EPI_GELU) {
                    vx = 0.5f * vx * (1.f + erff(vx * 0.70710678118654752f));
                    vy = 0.5f * vy * (1.f + erff(vy * 0.70710678118654752f));
                }
                if (EPI == EPI_ADD || EPI == EPI_PROJ) {
                    float2 rv = *(const float2*)(resid + (size_t)dstrow * Nn + col);
                    vx += rv.x; vy += rv.y;
                }
                float2 ov; ov.x = vx; ov.y = vy;
                *(float2*)(Cout + (size_t)dstrow * Nn + col) = ov;
            }
        }
    }
}

// ---------------- windowed attention ----------------
#define KSTR 33   // padded k row stride: lane stride 33 -> conflict-free
__global__ __launch_bounds__(256)
void attn_kernel(const float* __restrict__ qkv, const float* __restrict__ rpb,
                 float* __restrict__ out) {
    __shared__ float q[NTOK * HDIM];
    __shared__ float k[NTOK * KSTR];
    __shared__ float v[NTOK * HDIM];
    __shared__ float sc[NTOK * 50];
    int bw = blockIdx.y;
    int hid = blockIdx.x;
    int tid = threadIdx.x;
    const float scale = 0.17677669529663687f;

    for (int idx = tid; idx < NTOK * HDIM; idx += 256) {
        int n = idx >> 5, d = idx & 31;
        size_t base = (size_t)(bw * NTOK + n) * QKVC + hid * HDIM + d;
        q[idx] = qkv[base] * scale;
        k[n * KSTR + d] = qkv[base + CC];
        v[idx] = qkv[base + 2 * CC];
    }
    __syncthreads();

    int wi = bw & 63;
    int wr = wi >> 3, wc = wi & 7;
    for (int p = tid; p < NTOK * NTOK; p += 256) {
        int i = p / NTOK, j = p - i * NTOK;
        const float* qr = q + i * HDIM;
        const float* kr = k + j * KSTR;
        float s = 0.f;
        #pragma unroll
        for (int d = 0; d < HDIM; d++) s += qr[d] * kr[d];
        int ri = i / 7, ci = i - ri * 7;
        int rj = j / 7, cj = j - rj * 7;
        int bidx = (ri - rj + 6) * 13 + (ci - cj + 6);
        s += rpb[bidx * NHD + hid];
        int hi = wr * 7 + ri, wci = wc * 7 + ci;
        int hj = wr * 7 + rj, wcj = wc * 7 + cj;
        int regi = (hi < 49 ? 0 : (hi < 53 ? 1 : 2)) * 3 + (wci < 49 ? 0 : (wci < 53 ? 1 : 2));
        int regj = (hj < 49 ? 0 : (hj < 53 ? 1 : 2)) * 3 + (wcj < 49 ? 0 : (wcj < 53 ? 1 : 2));
        if (regi != regj) s -= 100.f;
        sc[i * 50 + j] = s;
    }
    __syncthreads();

    if (tid < NTOK) {
        float mx = -1e30f;
        #pragma unroll 7
        for (int j = 0; j < NTOK; j++) mx = fmaxf(mx, sc[tid * 50 + j]);
        float sum = 0.f;
        #pragma unroll 7
        for (int j = 0; j < NTOK; j++) {
            float e = __expf(sc[tid * 50 + j] - mx);
            sc[tid * 50 + j] = e;
            sum += e;
        }
        float inv = 1.f / sum;
        #pragma unroll 7
        for (int j = 0; j < NTOK; j++) sc[tid * 50 + j] *= inv;
    }
    __syncthreads();

    for (int idx = tid; idx < NTOK * HDIM; idx += 256) {
        int i = idx >> 5, d = idx & 31;
        float s = 0.f;
        #pragma unroll 7
        for (int j = 0; j < NTOK; j++) s += sc[i * 50 + j] * v[j * HDIM + d];
        out[(size_t)(bw * NTOK + i) * CC + hid * HDIM + d] = s;
    }
}

// ---------------- launch ----------------
extern "C" void kernel_launch(void* const* d_in, const int* in_sizes, int n_in,
                              void* d_out, int out_size) {
    const float* x      = (const float*)d_in[0];
    const float* g1     = (const float*)d_in[1];
    const float* b1     = (const float*)d_in[2];
    const float* w_qkv  = (const float*)d_in[3];
    const float* b_qkv  = (const float*)d_in[4];
    const float* w_proj = (const float*)d_in[5];
    const float* b_proj = (const float*)d_in[6];
    const float* rpb    = (const float*)d_in[7];
    const float* g2     = (const float*)d_in[8];
    const float* b2     = (const float*)d_in[9];
    const float* w1     = (const float*)d_in[10];
    const float* bm1    = (const float*)d_in[11];
    const float* w2     = (const float*)d_in[12];
    const float* bm2    = (const float*)d_in[13];
    float* out = (float*)d_out;

    float *bufA = nullptr, *bufB = nullptr;
    cudaGetSymbolAddress((void**)&bufA, g_bufA);
    cudaGetSymbolAddress((void**)&bufB, g_bufB);

    static bool attrSet = false;
    if (!attrSet) {
        cudaFuncSetAttribute(gemm_tc<EPI_BIAS>, cudaFuncAttributeMaxDynamicSharedMemorySize, SMEM_BYTES);
        cudaFuncSetAttribute(gemm_tc<EPI_GELU>, cudaFuncAttributeMaxDynamicSharedMemorySize, SMEM_BYTES);
        cudaFuncSetAttribute(gemm_tc<EPI_ADD>,  cudaFuncAttributeMaxDynamicSharedMemorySize, SMEM_BYTES);
        cudaFuncSetAttribute(gemm_tc<EPI_PROJ>, cudaFuncAttributeMaxDynamicSharedMemorySize, SMEM_BYTES);
        attrSet = true;
    }

    // 1) LN1 + roll + window partition -> bufB
    ln_kernel<true><<<TTOT, 128>>>(x, g1, b1, bufB);
    // 2) QKV GEMM -> bufA
    gemm_tc<EPI_BIAS><<<dim3(QKVC / 128, TTOT / 128), 256, SMEM_BYTES>>>(
        bufB, w_qkv, b_qkv, bufA, nullptr, TTOT, QKVC, CC);
    // 3) windowed attention -> bufB
    attn_kernel<<<dim3(NHD, BWIN), 256>>>(bufA, rpb, bufB);
    // 4) proj + window reverse + roll + residual -> out
    gemm_tc<EPI_PROJ><<<dim3(CC / 128, TTOT / 128), 256, SMEM_BYTES>>>(
        bufB, w_proj, b_proj, out, x, TTOT, CC, CC);
    // 5) LN2 -> bufB
    ln_kernel<false><<<TTOT, 128>>>(out, g2, b2, bufB);
    // 6) FC1 + GELU -> bufA
    gemm_tc<EPI_GELU><<<dim3(HIDN / 128, TTOT / 128), 256, SMEM_BYTES>>>(
        bufB, w1, bm1, bufA, nullptr, TTOT, HIDN, CC);
    // 7) FC2 + residual -> out
    gemm_tc<EPI_ADD><<<dim3(CC / 128, TTOT / 128), 256, SMEM_BYTES>>>(
        bufA, w2, bm2, out, out, TTOT, CC, HIDN);
}

// round 7
// speedup vs baseline: 4.5365x; 1.6140x over previous
#include <cuda_runtime.h>
#include <cuda_fp16.h>
#include <math.h>
#include <stdint.h>

// ---------------- problem constants ----------------
#define BB   32
#define HH   56
#define WWI  56
#define CC   384
#define NHD  12
#define HDIM 32
#define WSZ  7
#define SSZ  3
#define NTOK 49
#define NWIN 64
#define HIDN 1536
#define TTOT (BB*HH*WWI) // 100352
#define BWIN (BB*NWIN)   // 2048
#define QKVC (3*CC)      // 1152

// ---------------- scratch ----------------
__device__ __half g_bufA[(size_t)TTOT * HIDN];  // qkv out / mlp mid (half)
__device__ __half g_bufB[(size_t)TTOT * CC];    // LN out / attn out (half)
__device__ __half g_wT[1769472];                // transposed weights [N][K] half
#define WT_QKV  0
#define WT_PROJ 442368
#define WT_W1   589824
#define WT_W2   1179648

__device__ __forceinline__ int win2img(int r) {
    int bw = r / NTOK, n = r % NTOK;
    int b  = bw >> 6, wi = bw & 63;
    int wr = wi >> 3, wc = wi & 7;
    int nr = n / WSZ,  nc = n % WSZ;
    int hs = wr * WSZ + nr, ws = wc * WSZ + nc;
    int h = hs + SSZ; if (h >= HH)  h -= HH;
    int w = ws + SSZ; if (w >= WWI) w -= WWI;
    return (b * HH + h) * WWI + w;
}

// ---------------- weight transpose+convert: dst[n][k] = (half)src[k][n] ----------------
__global__ void transpose_k(const float* __restrict__ src, __half* __restrict__ dst,
                            int K, int N) {
    __shared__ float t[32][33];
    int kb = blockIdx.y * 32, nb = blockIdx.x * 32;
    int tx = threadIdx.x, ty = threadIdx.y; // 32 x 8
    #pragma unroll
    for (int i = ty; i < 32; i += 8)
        t[i][tx] = src[(size_t)(kb + i) * N + nb + tx];
    __syncthreads();
    #pragma unroll
    for (int i = ty; i < 32; i += 8)
        dst[(size_t)(nb + i) * K + kb + tx] = __float2half(t[tx][i]);
}

// ---------------- LayerNorm: fp32 in, half out ----------------
template<bool GATHER>
__global__ void ln_kernel(const float* __restrict__ in, const float* __restrict__ g,
                          const float* __restrict__ bta, __half* __restrict__ out) {
    int r = blockIdx.x;
    int src = GATHER ? win2img(r) : r;
    const float4* xr = (const float4*)(in + (size_t)src * CC);
    int t = threadIdx.x;  // 0..95
    float4 v = xr[t];
    float s = v.x + v.y + v.z + v.w;
    float q = v.x * v.x + v.y * v.y + v.z * v.z + v.w * v.w;
    #pragma unroll
    for (int o = 16; o; o >>= 1) {
        s += __shfl_xor_sync(0xffffffffu, s, o);
        q += __shfl_xor_sync(0xffffffffu, q, o);
    }
    __shared__ float ss[3], qq[3];
    int wid = t >> 5, lid = t & 31;
    if (!lid) { ss[wid] = s; qq[wid] = q; }
    __syncthreads();
    s = ss[0] + ss[1] + ss[2];
    q = qq[0] + qq[1] + qq[2];
    float mean = s * (1.0f / CC);
    float var  = q * (1.0f / CC) - mean * mean;
    float inv  = rsqrtf(var + 1e-5f);
    float4 gv = ((const float4*)g)[t];
    float4 bv = ((const float4*)bta)[t];
    float ox = (v.x - mean) * inv * gv.x + bv.x;
    float oy = (v.y - mean) * inv * gv.y + bv.y;
    float oz = (v.z - mean) * inv * gv.z + bv.z;
    float ow = (v.w - mean) * inv * gv.w + bv.w;
    __half2* orow = (__half2*)(out + (size_t)r * CC);
    orow[2 * t]     = __floats2half2_rn(ox, oy);
    orow[2 * t + 1] = __floats2half2_rn(oz, ow);
}

// ---------------- fp16 tensor-core GEMM (cp.async + ldmatrix, 3-stage) ----------------
enum { EPI_BIAS = 0, EPI_GELU = 1, EPI_ADD = 2, EPI_PROJ = 3 };

#define KC    32                 // halfs per k-chunk
#define NSTG  3
#define STG_B 16384              // A 8KB + B 8KB per stage
#define GSMEM (NSTG * STG_B)     // 49152

__device__ __forceinline__ void cp_async16(uint32_t saddr, const void* gptr) {
    asm volatile("cp.async.cg.shared.global [%0], [%1], 16;" :: "r"(saddr), "l"(gptr));
}
__device__ __forceinline__ void cp_commit() {
    asm volatile("cp.async.commit_group;");
}
__device__ __forceinline__ void cp_wait1() {
    asm volatile("cp.async.wait_group 1;");
}
#define LDSM_X4(r0, r1, r2, r3, addr) \
    asm volatile("ldmatrix.sync.aligned.m8n8.x4.shared.b16 {%0,%1,%2,%3}, [%4];" \
                 : "=r"(r0), "=r"(r1), "=r"(r2), "=r"(r3) : "r"(addr))

__device__ __forceinline__ void mma_f16(float* c, const uint32_t* a, const uint32_t* b) {
    asm volatile(
        "mma.sync.aligned.m16n8k16.row.col.f32.f16.f16.f32 "
        "{%0,%1,%2,%3}, {%4,%5,%6,%7}, {%8,%9}, {%0,%1,%2,%3};"
        : "+f"(c[0]), "+f"(c[1]), "+f"(c[2]), "+f"(c[3])
        : "r"(a[0]), "r"(a[1]), "r"(a[2]), "r"(a[3]), "r"(b[0]), "r"(b[1]));
}

// CTA 128x128, 8 warps (4x2), warp tile 32x64, K streamed in 32-half chunks.
template<int EPI>
__global__ __launch_bounds__(256, 2)
void gemm_f16(const __half* __restrict__ A, const __half* __restrict__ Bt,
              const float* __restrict__ bias, void* __restrict__ CoutV,
              const float* __restrict__ resid, int Nn, int K) {
    constexpr bool HALF_OUT = (EPI == EPI_BIAS || EPI == EPI_GELU);
    extern __shared__ __align__(128) char smem[];
    uint32_t sb = (uint32_t)__cvta_generic_to_shared(smem);

    int tid = threadIdx.x;
    int lane = tid & 31, warp = tid >> 5;
    int g = lane >> 2, t = lane & 3;
    int wm = (warp >> 1) * 32, wn = (warp & 1) * 64;
    int rowBase = blockIdx.y * 128, colBase = blockIdx.x * 128;
    int nch = K / KC;

    // producer geometry: thread -> row (t>>1), two 16B chunks
    int pr = tid >> 1;
    int pc0 = (tid & 1) * 2;
    const __half* ag = A  + (size_t)(rowBase + pr) * K + pc0 * 8;
    const __half* bg = Bt + (size_t)(colBase + pr) * K + pc0 * 8;
    uint32_t aoffp[2], boffp[2];
    #pragma unroll
    for (int j = 0; j < 2; j++) {
        int ch = pc0 + j;
        int sw = ch ^ (pr & 3) ^ ((pr >> 2) & 3);
        aoffp[j] = pr * 64 + sw * 16;
        boffp[j] = 8192 + pr * 64 + sw * 16;
    }

    // ldmatrix fragment addresses
    uint32_t aoffs[2][2], boffs[4][2];
    #pragma unroll
    for (int mt = 0; mt < 2; mt++)
        #pragma unroll
        for (int ks = 0; ks < 2; ks++) {
            int row = wm + mt * 16 + (lane & 7) + ((lane >> 3) & 1) * 8;
            int ch  = 2 * ks + ((lane >> 4) & 1);
            int sw  = ch ^ (row & 3) ^ ((row >> 2) & 3);
            aoffs[mt][ks] = row * 64 + sw * 16;
        }
    #pragma unroll
    for (int p = 0; p < 4; p++)
        #pragma unroll
        for (int ks = 0; ks < 2; ks++) {
            int n  = wn + p * 16 + (lane & 7) + ((lane >> 4) & 1) * 8;
            int ch = 2 * ks + ((lane >> 3) & 1);
            int sw = ch ^ (n & 3) ^ ((n >> 2) & 3);
            boffs[p][ks] = 8192 + n * 64 + sw * 16;
        }

    float acc[2][8][4];
    #pragma unroll
    for (int mt = 0; mt < 2; mt++)
        #pragma unroll
        for (int nt = 0; nt < 8; nt++)
            #pragma unroll
            for (int j = 0; j < 4; j++) acc[mt][nt][j] = 0.f;

    // prologue: fill stages 0,1
    #pragma unroll
    for (int s = 0; s < NSTG - 1; s++) {
        uint32_t stg = sb + s * STG_B;
        #pragma unroll
        for (int j = 0; j < 2; j++) {
            cp_async16(stg + aoffp[j], ag + s * KC + j * 8);
            cp_async16(stg + boffp[j], bg + s * KC + j * 8);
        }
        cp_commit();
    }

    int stage = 0;
    for (int it = 0; it < nch; ++it) {
        cp_wait1();
        __syncthreads();

        uint32_t sbase = sb + stage * STG_B;
        #pragma unroll
        for (int ks = 0; ks < 2; ks++) {
            uint32_t af[2][4], bf[8][2];
            #pragma unroll
            for (int mt = 0; mt < 2; mt++)
                LDSM_X4(af[mt][0], af[mt][1], af[mt][2], af[mt][3], sbase + aoffs[mt][ks]);
            #pragma unroll
            for (int p = 0; p < 4; p++)
                LDSM_X4(bf[2 * p][0], bf[2 * p][1], bf[2 * p + 1][0], bf[2 * p + 1][1],
                        sbase + boffs[p][ks]);
            #pragma unroll
            for (int mt = 0; mt < 2; mt++)
                #pragma unroll
                for (int nt = 0; nt < 8; nt++)
                    mma_f16(acc[mt][nt], af[mt], bf[nt]);
        }

        int nk = it + NSTG - 1;
        if (nk < nch) {
            int ns = stage + (NSTG - 1); if (ns >= NSTG) ns -= NSTG;
            uint32_t stg = sb + ns * STG_B;
            #pragma unroll
            for (int j = 0; j < 2; j++) {
                cp_async16(stg + aoffp[j], ag + nk * KC + j * 8);
                cp_async16(stg + boffp[j], bg + nk * KC + j * 8);
            }
        }
        cp_commit();
        stage = stage + 1; if (stage == NSTG) stage = 0;
    }

    // epilogue
    #pragma unroll
    for (int mt = 0; mt < 2; mt++) {
        #pragma unroll
        for (int p = 0; p < 2; p++) {
            int r = rowBase + wm + mt * 16 + g + p * 8;
            int dstrow = (EPI == EPI_PROJ) ? win2img(r) : r;
            #pragma unroll
            for (int nt = 0; nt < 8; nt++) {
                int col = colBase + wn + nt * 8 + t * 2;
                float2 bv = *(const float2*)(bias + col);
                float vx = acc[mt][nt][p * 2 + 0] + bv.x;
                float vy = acc[mt][nt][p * 2 + 1] + bv.y;
                if (EPI == EPI_GELU) {
                    vx = 0.5f * vx * (1.f + erff(vx * 0.70710678118654752f));
                    vy = 0.5f * vy * (1.f + erff(vy * 0.70710678118654752f));
                }
                if (EPI == EPI_ADD || EPI == EPI_PROJ) {
                    const float* rrow = resid + (size_t)dstrow * Nn + col;
                    float2 rv = *(const float2*)rrow;
                    vx += rv.x; vy += rv.y;
                }
                if (HALF_OUT) {
                    __half* crow = (__half*)CoutV + (size_t)dstrow * Nn + col;
                    *(__half2*)crow = __floats2half2_rn(vx, vy);
                } else {
                    float* crow = (float*)CoutV + (size_t)dstrow * Nn + col;
                    float2 ov; ov.x = vx; ov.y = vy;
                    *(float2*)crow = ov;
                }
            }
        }
    }
}

// ---------------- windowed attention (half in/out, fp32 math) ----------------
#define KSTR 33
__global__ __launch_bounds__(256)
void attn_kernel(const __half* __restrict__ qkv, const float* __restrict__ rpb,
                 __half* __restrict__ out) {
    __shared__ float q[NTOK * HDIM];
    __shared__ float k[NTOK * KSTR];
    __shared__ float v[NTOK * HDIM];
    __shared__ float sc[NTOK * 50];
    int bw = blockIdx.y;
    int hid = blockIdx.x;
    int tid = threadIdx.x;
    const float scale = 0.17677669529663687f;

    for (int idx = tid; idx < NTOK * 16; idx += 256) {
        int n = idx >> 4, dp = idx & 15;
        size_t base = (size_t)(bw * NTOK + n) * QKVC + hid * HDIM + dp * 2;
        float2 qf = __half22float2(*(const __half2*)(qkv + base));
        float2 kf = __half22float2(*(const __half2*)(qkv + base + CC));
        float2 vf = __half22float2(*(const __half2*)(qkv + base + 2 * CC));
        q[n * HDIM + 2 * dp]     = qf.x * scale;
        q[n * HDIM + 2 * dp + 1] = qf.y * scale;
        k[n * KSTR + 2 * dp]     = kf.x;
        k[n * KSTR + 2 * dp + 1] = kf.y;
        v[n * HDIM + 2 * dp]     = vf.x;
        v[n * HDIM + 2 * dp + 1] = vf.y;
    }
    __syncthreads();

    int wi = bw & 63;
    int wr = wi >> 3, wc = wi & 7;
    for (int p = tid; p < NTOK * NTOK; p += 256) {
        int i = p / NTOK, j = p - i * NTOK;
        const float* qr = q + i * HDIM;
        const float* kr = k + j * KSTR;
        float s = 0.f;
        #pragma unroll
        for (int d = 0; d < HDIM; d++) s += qr[d] * kr[d];
        int ri = i / 7, ci = i - ri * 7;
        int rj = j / 7, cj = j - rj * 7;
        int bidx = (ri - rj + 6) * 13 + (ci - cj + 6);
        s += rpb[bidx * NHD + hid];
        int hi = wr * 7 + ri, wci = wc * 7 + ci;
        int hj = wr * 7 + rj, wcj = wc * 7 + cj;
        int regi = (hi < 49 ? 0 : (hi < 53 ? 1 : 2)) * 3 + (wci < 49 ? 0 : (wci < 53 ? 1 : 2));
        int regj = (hj < 49 ? 0 : (hj < 53 ? 1 : 2)) * 3 + (wcj < 49 ? 0 : (wcj < 53 ? 1 : 2));
        if (regi != regj) s -= 100.f;
        sc[i * 50 + j] = s;
    }
    __syncthreads();

    if (tid < NTOK) {
        float mx = -1e30f;
        #pragma unroll 7
        for (int j = 0; j < NTOK; j++) mx = fmaxf(mx, sc[tid * 50 + j]);
        float sum = 0.f;
        #pragma unroll 7
        for (int j = 0; j < NTOK; j++) {
            float e = __expf(sc[tid * 50 + j] - mx);
            sc[tid * 50 + j] = e;
            sum += e;
        }
        float inv = 1.f / sum;
        #pragma unroll 7
        for (int j = 0; j < NTOK; j++) sc[tid * 50 + j] *= inv;
    }
    __syncthreads();

    for (int idx = tid; idx < NTOK * 16; idx += 256) {
        int i = idx >> 4, dp = idx & 15;
        float s0 = 0.f, s1 = 0.f;
        const float* si = sc + i * 50;
        #pragma unroll 7
        for (int j = 0; j < NTOK; j++) {
            float pw = si[j];
            s0 += pw * v[j * HDIM + 2 * dp];
            s1 += pw * v[j * HDIM + 2 * dp + 1];
        }
        __half* op = out + (size_t)(bw * NTOK + i) * CC + hid * HDIM + dp * 2;
        *(__half2*)op = __floats2half2_rn(s0, s1);
    }
}

// ---------------- launch ----------------
extern "C" void kernel_launch(void* const* d_in, const int* in_sizes, int n_in,
                              void* d_out, int out_size) {
    const float* x      = (const float*)d_in[0];
    const float* g1     = (const float*)d_in[1];
    const float* b1     = (const float*)d_in[2];
    const float* w_qkv  = (const float*)d_in[3];
    const float* b_qkv  = (const float*)d_in[4];
    const float* w_proj = (const float*)d_in[5];
    const float* b_proj = (const float*)d_in[6];
    const float* rpb    = (const float*)d_in[7];
    const float* g2     = (const float*)d_in[8];
    const float* b2     = (const float*)d_in[9];
    const float* w1     = (const float*)d_in[10];
    const float* bm1    = (const float*)d_in[11];
    const float* w2     = (const float*)d_in[12];
    const float* bm2    = (const float*)d_in[13];
    float* out = (float*)d_out;

    __half *bufA = nullptr, *bufB = nullptr, *wT = nullptr;
    cudaGetSymbolAddress((void**)&bufA, g_bufA);
    cudaGetSymbolAddress((void**)&bufB, g_bufB);
    cudaGetSymbolAddress((void**)&wT, g_wT);

    cudaFuncSetAttribute(gemm_f16<EPI_BIAS>, cudaFuncAttributeMaxDynamicSharedMemorySize, GSMEM);
    cudaFuncSetAttribute(gemm_f16<EPI_GELU>, cudaFuncAttributeMaxDynamicSharedMemorySize, GSMEM);
    cudaFuncSetAttribute(gemm_f16<EPI_ADD>,  cudaFuncAttributeMaxDynamicSharedMemorySize, GSMEM);
    cudaFuncSetAttribute(gemm_f16<EPI_PROJ>, cudaFuncAttributeMaxDynamicSharedMemorySize, GSMEM);

    // 0) transpose + convert weights -> half [N][K]
    dim3 tb(32, 8);
    transpose_k<<<dim3(QKVC / 32, CC / 32),   tb>>>(w_qkv,  wT + WT_QKV,  CC,   QKVC);
    transpose_k<<<dim3(CC / 32,   CC / 32),   tb>>>(w_proj, wT + WT_PROJ, CC,   CC);
    transpose_k<<<dim3(HIDN / 32, CC / 32),   tb>>>(w1,     wT + WT_W1,   CC,   HIDN);
    transpose_k<<<dim3(CC / 32,   HIDN / 32), tb>>>(w2,     wT + WT_W2,   HIDN, CC);

    // 1) LN1 + roll + window partition -> bufB (half)
    ln_kernel<true><<<TTOT, 96>>>(x, g1, b1, bufB);
    // 2) QKV GEMM -> bufA (half)
    gemm_f16<EPI_BIAS><<<dim3(QKVC / 128, TTOT / 128), 256, GSMEM>>>(
        bufB, wT + WT_QKV, b_qkv, bufA, nullptr, QKVC, CC);
    // 3) windowed attention -> bufB (half)
    attn_kernel<<<dim3(NHD, BWIN), 256>>>(bufA, rpb, bufB);
    // 4) proj + window reverse + roll + residual(x) -> out (fp32)
    gemm_f16<EPI_PROJ><<<dim3(CC / 128, TTOT / 128), 256, GSMEM>>>(
        bufB, wT + WT_PROJ, b_proj, out, x, CC, CC);
    // 5) LN2 -> bufB (half)
    ln_kernel<false><<<TTOT, 96>>>(out, g2, b2, bufB);
    // 6) FC1 + GELU -> bufA (half)
    gemm_f16<EPI_GELU><<<dim3(HIDN / 128, TTOT / 128), 256, GSMEM>>>(
        bufB, wT + WT_W1, bm1, bufA, nullptr, HIDN, CC);
    // 7) FC2 + residual(out) -> out (fp32)
    gemm_f16<EPI_ADD><<<dim3(CC / 128, TTOT / 128), 256, GSMEM>>>(
        bufA, wT + WT_W2, bm2, out, out, CC, HIDN);
}

// round 9
// speedup vs baseline: 6.6943x; 1.4756x over previous
#include <cuda_runtime.h>
#include <cuda_fp16.h>
#include <math.h>
#include <stdint.h>

// ---------------- problem constants ----------------
#define BB   32
#define HH   56
#define WWI  56
#define CC   384
#define NHD  12
#define HDIM 32
#define WSZ  7
#define SSZ  3
#define NTOK 49
#define NWIN 64
#define HIDN 1536
#define TTOT (BB*HH*WWI) // 100352
#define BWIN (BB*NWIN)   // 2048
#define QKVC (3*CC)      // 1152

// ---------------- scratch ----------------
__device__ __half g_bufA[(size_t)TTOT * HIDN];  // qkv out / mlp mid (half)
__device__ __half g_bufB[(size_t)TTOT * CC];    // LN out / attn out (half)
__device__ __half g_wT[1769472];                // transposed weights [N][K] half
#define WT_QKV  0
#define WT_PROJ 442368
#define WT_W1   589824
#define WT_W2   1179648

__device__ __forceinline__ int win2img(int r) {
    int bw = r / NTOK, n = r % NTOK;
    int b  = bw >> 6, wi = bw & 63;
    int wr = wi >> 3, wc = wi & 7;
    int nr = n / WSZ,  nc = n % WSZ;
    int hs = wr * WSZ + nr, ws = wc * WSZ + nc;
    int h = hs + SSZ; if (h >= HH)  h -= HH;
    int w = ws + SSZ; if (w >= WWI) w -= WWI;
    return (b * HH + h) * WWI + w;
}

// ---------------- weight transpose+convert: dst[n][k] = (half)src[k][n] ----------------
__global__ void transpose_k(const float* __restrict__ src, __half* __restrict__ dst,
                            int K, int N) {
    __shared__ float t[32][33];
    int kb = blockIdx.y * 32, nb = blockIdx.x * 32;
    int tx = threadIdx.x, ty = threadIdx.y; // 32 x 8
    #pragma unroll
    for (int i = ty; i < 32; i += 8)
        t[i][tx] = src[(size_t)(kb + i) * N + nb + tx];
    __syncthreads();
    #pragma unroll
    for (int i = ty; i < 32; i += 8)
        dst[(size_t)(nb + i) * K + kb + tx] = __float2half(t[tx][i]);
}

// ---------------- LayerNorm: fp32 in, half out ----------------
template<bool GATHER>
__global__ void ln_kernel(const float* __restrict__ in, const float* __restrict__ g,
                          const float* __restrict__ bta, __half* __restrict__ out) {
    int r = blockIdx.x;
    int src = GATHER ? win2img(r) : r;
    const float4* xr = (const float4*)(in + (size_t)src * CC);
    int t = threadIdx.x;  // 0..95
    float4 v = xr[t];
    float s = v.x + v.y + v.z + v.w;
    float q = v.x * v.x + v.y * v.y + v.z * v.z + v.w * v.w;
    #pragma unroll
    for (int o = 16; o; o >>= 1) {
        s += __shfl_xor_sync(0xffffffffu, s, o);
        q += __shfl_xor_sync(0xffffffffu, q, o);
    }
    __shared__ float ss[3], qq[3];
    int wid = t >> 5, lid = t & 31;
    if (!lid) { ss[wid] = s; qq[wid] = q; }
    __syncthreads();
    s = ss[0] + ss[1] + ss[2];
    q = qq[0] + qq[1] + qq[2];
    float mean = s * (1.0f / CC);
    float var  = q * (1.0f / CC) - mean * mean;
    float inv  = rsqrtf(var + 1e-5f);
    float4 gv = ((const float4*)g)[t];
    float4 bv = ((const float4*)bta)[t];
    float ox = (v.x - mean) * inv * gv.x + bv.x;
    float oy = (v.y - mean) * inv * gv.y + bv.y;
    float oz = (v.z - mean) * inv * gv.z + bv.z;
    float ow = (v.w - mean) * inv * gv.w + bv.w;
    __half2* orow = (__half2*)(out + (size_t)r * CC);
    orow[2 * t]     = __floats2half2_rn(ox, oy);
    orow[2 * t + 1] = __floats2half2_rn(oz, ow);
}

// ---------------- fp16 tensor-core GEMM (cp.async + ldmatrix, 3-stage) ----------------
enum { EPI_BIAS = 0, EPI_GELU = 1, EPI_ADD = 2, EPI_PROJ = 3 };

#define KC    32                 // halfs per k-chunk
#define NSTG  3
#define STG_B 16384              // A 8KB + B 8KB per stage
#define GSMEM (NSTG * STG_B)     // 49152

__device__ __forceinline__ void cp_async16(uint32_t saddr, const void* gptr) {
    asm volatile("cp.async.cg.shared.global [%0], [%1], 16;" :: "r"(saddr), "l"(gptr));
}
__device__ __forceinline__ void cp_commit() {
    asm volatile("cp.async.commit_group;");
}
__device__ __forceinline__ void cp_wait1() {
    asm volatile("cp.async.wait_group 1;");
}
#define LDSM_X4(r0, r1, r2, r3, addr) \
    asm volatile("ldmatrix.sync.aligned.m8n8.x4.shared.b16 {%0,%1,%2,%3}, [%4];" \
                 : "=r"(r0), "=r"(r1), "=r"(r2), "=r"(r3) : "r"(addr))

__device__ __forceinline__ void mma_f16(float* c, const uint32_t* a, const uint32_t* b) {
    asm volatile(
        "mma.sync.aligned.m16n8k16.row.col.f32.f16.f16.f32 "
        "{%0,%1,%2,%3}, {%4,%5,%6,%7}, {%8,%9}, {%0,%1,%2,%3};"
        : "+f"(c[0]), "+f"(c[1]), "+f"(c[2]), "+f"(c[3])
        : "r"(a[0]), "r"(a[1]), "r"(a[2]), "r"(a[3]), "r"(b[0]), "r"(b[1]));
}

// CTA 128x128, 8 warps (4x2), warp tile 32x64, K streamed in 32-half chunks.
template<int EPI>
__global__ __launch_bounds__(256, 2)
void gemm_f16(const __half* __restrict__ A, const __half* __restrict__ Bt,
              const float* __restrict__ bias, void* __restrict__ CoutV,
              const float* __restrict__ resid, int Nn, int K) {
    constexpr bool HALF_OUT = (EPI == EPI_BIAS || EPI == EPI_GELU);
    extern __shared__ __align__(128) char smem[];
    uint32_t sb = (uint32_t)__cvta_generic_to_shared(smem);

    int tid = threadIdx.x;
    int lane = tid & 31, warp = tid >> 5;
    int g = lane >> 2, t = lane & 3;
    int wm = (warp >> 1) * 32, wn = (warp & 1) * 64;
    int rowBase = blockIdx.y * 128, colBase = blockIdx.x * 128;
    int nch = K / KC;

    int pr = tid >> 1;
    int pc0 = (tid & 1) * 2;
    const __half* ag = A  + (size_t)(rowBase + pr) * K + pc0 * 8;
    const __half* bg = Bt + (size_t)(colBase + pr) * K + pc0 * 8;
    uint32_t aoffp[2], boffp[2];
    #pragma unroll
    for (int j = 0; j < 2; j++) {
        int ch = pc0 + j;
        int sw = ch ^ (pr & 3) ^ ((pr >> 2) & 3);
        aoffp[j] = pr * 64 + sw * 16;
        boffp[j] = 8192 + pr * 64 + sw * 16;
    }

    uint32_t aoffs[2][2], boffs[4][2];
    #pragma unroll
    for (int mt = 0; mt < 2; mt++)
        #pragma unroll
        for (int ks = 0; ks < 2; ks++) {
            int row = wm + mt * 16 + (lane & 7) + ((lane >> 3) & 1) * 8;
            int ch  = 2 * ks + ((lane >> 4) & 1);
            int sw  = ch ^ (row & 3) ^ ((row >> 2) & 3);
            aoffs[mt][ks] = row * 64 + sw * 16;
        }
    #pragma unroll
    for (int p = 0; p < 4; p++)
        #pragma unroll
        for (int ks = 0; ks < 2; ks++) {
            int n  = wn + p * 16 + (lane & 7) + ((lane >> 4) & 1) * 8;
            int ch = 2 * ks + ((lane >> 3) & 1);
            int sw = ch ^ (n & 3) ^ ((n >> 2) & 3);
            boffs[p][ks] = 8192 + n * 64 + sw * 16;
        }

    float acc[2][8][4];
    #pragma unroll
    for (int mt = 0; mt < 2; mt++)
        #pragma unroll
        for (int nt = 0; nt < 8; nt++)
            #pragma unroll
            for (int j = 0; j < 4; j++) acc[mt][nt][j] = 0.f;

    #pragma unroll
    for (int s = 0; s < NSTG - 1; s++) {
        uint32_t stg = sb + s * STG_B;
        #pragma unroll
        for (int j = 0; j < 2; j++) {
            cp_async16(stg + aoffp[j], ag + s * KC + j * 8);
            cp_async16(stg + boffp[j], bg + s * KC + j * 8);
        }
        cp_commit();
    }

    int stage = 0;
    for (int it = 0; it < nch; ++it) {
        cp_wait1();
        __syncthreads();

        uint32_t sbase = sb + stage * STG_B;
        #pragma unroll
        for (int ks = 0; ks < 2; ks++) {
            uint32_t af[2][4], bf[8][2];
            #pragma unroll
            for (int mt = 0; mt < 2; mt++)
                LDSM_X4(af[mt][0], af[mt][1], af[mt][2], af[mt][3], sbase + aoffs[mt][ks]);
            #pragma unroll
            for (int p = 0; p < 4; p++)
                LDSM_X4(bf[2 * p][0], bf[2 * p][1], bf[2 * p + 1][0], bf[2 * p + 1][1],
                        sbase + boffs[p][ks]);
            #pragma unroll
            for (int mt = 0; mt < 2; mt++)
                #pragma unroll
                for (int nt = 0; nt < 8; nt++)
                    mma_f16(acc[mt][nt], af[mt], bf[nt]);
        }

        int nk = it + NSTG - 1;
        if (nk < nch) {
            int ns = stage + (NSTG - 1); if (ns >= NSTG) ns -= NSTG;
            uint32_t stg = sb + ns * STG_B;
            #pragma unroll
            for (int j = 0; j < 2; j++) {
                cp_async16(stg + aoffp[j], ag + nk * KC + j * 8);
                cp_async16(stg + boffp[j], bg + nk * KC + j * 8);
            }
        }
        cp_commit();
        stage = stage + 1; if (stage == NSTG) stage = 0;
    }

    #pragma unroll
    for (int mt = 0; mt < 2; mt++) {
        #pragma unroll
        for (int p = 0; p < 2; p++) {
            int r = rowBase + wm + mt * 16 + g + p * 8;
            int dstrow = (EPI == EPI_PROJ) ? win2img(r) : r;
            #pragma unroll
            for (int nt = 0; nt < 8; nt++) {
                int col = colBase + wn + nt * 8 + t * 2;
                float2 bv = *(const float2*)(bias + col);
                float vx = acc[mt][nt][p * 2 + 0] + bv.x;
                float vy = acc[mt][nt][p * 2 + 1] + bv.y;
                if (EPI == EPI_GELU) {
                    vx = 0.5f * vx * (1.f + erff(vx * 0.70710678118654752f));
                    vy = 0.5f * vy * (1.f + erff(vy * 0.70710678118654752f));
                }
                if (EPI == EPI_ADD || EPI == EPI_PROJ) {
                    const float* rrow = resid + (size_t)dstrow * Nn + col;
                    float2 rv = *(const float2*)rrow;
                    vx += rv.x; vy += rv.y;
                }
                if (HALF_OUT) {
                    __half* crow = (__half*)CoutV + (size_t)dstrow * Nn + col;
                    *(__half2*)crow = __floats2half2_rn(vx, vy);
                } else {
                    float* crow = (float*)CoutV + (size_t)dstrow * Nn + col;
                    float2 ov; ov.x = vx; ov.y = vy;
                    *(float2*)crow = ov;
                }
            }
        }
    }
}

// ---------------- tensor-core windowed attention ----------------
// Block = (window, head), 128 threads / 4 warps, warp owns a 16-row m-tile.
// smem rows are 128B with XOR swizzle: phys_chunk = chunk ^ (row & 7).
__global__ __launch_bounds__(128)
void attn_tc(const __half* __restrict__ qkv, const float* __restrict__ rpb,
             __half* __restrict__ out) {
    __shared__ __align__(16) char sm[28672];   // Q 8K | K 8K | Vt 4K | P 8K
    __shared__ float rpbs[169];
    uint32_t sbQ = (uint32_t)__cvta_generic_to_shared(sm);
    uint32_t sbK = sbQ + 8192;
    uint32_t sbVt = sbQ + 16384;
    uint32_t sbP = sbQ + 20480;

    int bw = blockIdx.y;   // window
    int hid = blockIdx.x;  // head
    int tid = threadIdx.x;
    int w = tid >> 5, lane = tid & 31, g = lane >> 2, t = lane & 3;
    const float scale = 0.17677669529663687f;

    // zero Q,K,Vt (pad rows must be 0)
    for (int i = tid; i < 5120; i += 128) ((uint32_t*)sm)[i] = 0;
    for (int i = tid; i < 169; i += 128) rpbs[i] = rpb[i * NHD + hid];
    __syncthreads();

    // load Q,K (swizzled rows), V transposed into Vt[dim][tok]
    for (int idx = tid; idx < NTOK * 4; idx += 128) {
        int tok = idx >> 2, c = idx & 3;
        const __half* src = qkv + (size_t)(bw * NTOK + tok) * QKVC + hid * HDIM + c * 8;
        uint32_t off = tok * 128 + ((c ^ (tok & 7)) << 4);
        *(uint4*)(sm + (off)) = *(const uint4*)src;                    // Q
        *(uint4*)(sm + 8192 + off) = *(const uint4*)(src + CC);       // K
        uint4 vv = *(const uint4*)(src + 2 * CC);
        const __half* vh = (const __half*)&vv;
        #pragma unroll
        for (int d = 0; d < 8; d++) {
            int dim = c * 8 + d;
            *(__half*)(sm + 16384 + dim * 128 + ((((tok >> 3) ^ (dim & 7))) << 4)
                       + (tok & 7) * 2) = vh[d];
        }
    }
    __syncthreads();

    // ---- S = Q K^T (rows 16w..16w+15, cols 0..63) ----
    float sacc[8][4];
    #pragma unroll
    for (int nt = 0; nt < 8; nt++)
        #pragma unroll
        for (int j = 0; j < 4; j++) sacc[nt][j] = 0.f;

    int arow = w * 16 + (lane & 7) + ((lane >> 3) & 1) * 8;
    int bn7 = (lane & 7) + ((lane >> 4) & 1) * 8;
    #pragma unroll
    for (int ks = 0; ks < 2; ks++) {
        int ach = 2 * ks + ((lane >> 4) & 1);
        uint32_t af[4];
        LDSM_X4(af[0], af[1], af[2], af[3],
                sbQ + arow * 128 + ((ach ^ (arow & 7)) << 4));
        int bch = 2 * ks + ((lane >> 3) & 1);
        #pragma unroll
        for (int p = 0; p < 4; p++) {
            int n = p * 16 + bn7;
            uint32_t bf0[2], bf1[2];
            LDSM_X4(bf0[0], bf0[1], bf1[0], bf1[1],
                    sbK + n * 128 + ((bch ^ (n & 7)) << 4));
            mma_f16(sacc[2 * p], af, bf0);
            mma_f16(sacc[2 * p + 1], af, bf1);
        }
    }

    // ---- bias + mask + softmax (in regs), write P (half, swizzled) ----
    int wi = bw & 63;
    int wr = wi >> 3, wc = wi & 7;
    #pragma unroll
    for (int p = 0; p < 2; p++) {
        int i = w * 16 + g + p * 8;
        int ii = (i < 48) ? i : 48;
        int ri = ii / 7, ci = ii - ri * 7;
        int hi = wr * 7 + ri, wci = wc * 7 + ci;
        int regi = (hi < 49 ? 0 : (hi < 53 ? 1 : 2)) * 3 + (wci < 49 ? 0 : (wci < 53 ? 1 : 2));
        int rbase = (ri + 6) * 13 + (ci + 6);
        float sv[16];
        float mx = -1e30f;
        #pragma unroll
        for (int nt = 0; nt < 8; nt++) {
            #pragma unroll
            for (int q = 0; q < 2; q++) {
                int j = nt * 8 + t * 2 + q;
                float s = -1e30f;
                if (j < NTOK) {
                    int rj = j / 7, cj = j - rj * 7;
                    int hj = wr * 7 + rj, wcj = wc * 7 + cj;
                    int regj = (hj < 49 ? 0 : (hj < 53 ? 1 : 2)) * 3
                             + (wcj < 49 ? 0 : (wcj < 53 ? 1 : 2));
                    s = sacc[nt][p * 2 + q] * scale + rpbs[rbase - rj * 13 - cj];
                    if (regi != regj) s -= 100.f;
                }
                sv[nt * 2 + q] = s;
                mx = fmaxf(mx, s);
            }
        }
        mx = fmaxf(mx, __shfl_xor_sync(0xffffffffu, mx, 1));
        mx = fmaxf(mx, __shfl_xor_sync(0xffffffffu, mx, 2));
        float sum = 0.f;
        #pragma unroll
        for (int e = 0; e < 16; e++) {
            float ev = __expf(sv[e] - mx);
            sv[e] = ev;
            sum += ev;
        }
        sum += __shfl_xor_sync(0xffffffffu, sum, 1);
        sum += __shfl_xor_sync(0xffffffffu, sum, 2);
        float inv = 1.f / sum;
        #pragma unroll
        for (int nt = 0; nt < 8; nt++) {
            int j0 = nt * 8 + t * 2;
            uint32_t addr = sbP + i * 128 + ((nt ^ (i & 7)) << 4) + (j0 & 7) * 2;
            __half2 hv = __floats2half2_rn(sv[nt * 2] * inv, sv[nt * 2 + 1] * inv);
            asm volatile("st.shared.u32 [%0], %1;" :: "r"(addr),
                         "r"(*(const uint32_t*)&hv));
        }
    }
    __syncwarp();

    // ---- O = P V (K dim = 64, V pad rows are 0) ----
    float po[4][4];
    #pragma unroll
    for (int nt = 0; nt < 4; nt++)
        #pragma unroll
        for (int j = 0; j < 4; j++) po[nt][j] = 0.f;

    #pragma unroll
    for (int ks = 0; ks < 4; ks++) {
        int ach = 2 * ks + ((lane >> 4) & 1);
        uint32_t af[4];
        LDSM_X4(af[0], af[1], af[2], af[3],
                sbP + arow * 128 + ((ach ^ (arow & 7)) << 4));
        int bch = 2 * ks + ((lane >> 3) & 1);
        #pragma unroll
        for (int p = 0; p < 2; p++) {
            int n = p * 16 + bn7;   // dim rows of Vt (0..31)
            uint32_t vf0[2], vf1[2];
            LDSM_X4(vf0[0], vf0[1], vf1[0], vf1[1],
                    sbVt + n * 128 + ((bch ^ (n & 7)) << 4));
            mma_f16(po[2 * p], af, vf0);
            mma_f16(po[2 * p + 1], af, vf1);
        }
    }

    // ---- write O ----
    #pragma unroll
    for (int p = 0; p < 2; p++) {
        int tok = w * 16 + g + p * 8;
        if (tok < NTOK) {
            __half* orow = out + (size_t)(bw * NTOK + tok) * CC + hid * HDIM;
            #pragma unroll
            for (int nt = 0; nt < 4; nt++) {
                __half2 hv = __floats2half2_rn(po[nt][p * 2], po[nt][p * 2 + 1]);
                *(__half2*)(orow + nt * 8 + t * 2) = hv;
            }
        }
    }
}

// ---------------- launch ----------------
extern "C" void kernel_launch(void* const* d_in, const int* in_sizes, int n_in,
                              void* d_out, int out_size) {
    const float* x      = (const float*)d_in[0];
    const float* g1     = (const float*)d_in[1];
    const float* b1     = (const float*)d_in[2];
    const float* w_qkv  = (const float*)d_in[3];
    const float* b_qkv  = (const float*)d_in[4];
    const float* w_proj = (const float*)d_in[5];
    const float* b_proj = (const float*)d_in[6];
    const float* rpb    = (const float*)d_in[7];
    const float* g2     = (const float*)d_in[8];
    const float* b2     = (const float*)d_in[9];
    const float* w1     = (const float*)d_in[10];
    const float* bm1    = (const float*)d_in[11];
    const float* w2     = (const float*)d_in[12];
    const float* bm2    = (const float*)d_in[13];
    float* out = (float*)d_out;

    __half *bufA = nullptr, *bufB = nullptr, *wT = nullptr;
    cudaGetSymbolAddress((void**)&bufA, g_bufA);
    cudaGetSymbolAddress((void**)&bufB, g_bufB);
    cudaGetSymbolAddress((void**)&wT, g_wT);

    cudaFuncSetAttribute(gemm_f16<EPI_BIAS>, cudaFuncAttributeMaxDynamicSharedMemorySize, GSMEM);
    cudaFuncSetAttribute(gemm_f16<EPI_GELU>, cudaFuncAttributeMaxDynamicSharedMemorySize, GSMEM);
    cudaFuncSetAttribute(gemm_f16<EPI_ADD>,  cudaFuncAttributeMaxDynamicSharedMemorySize, GSMEM);
    cudaFuncSetAttribute(gemm_f16<EPI_PROJ>, cudaFuncAttributeMaxDynamicSharedMemorySize, GSMEM);

    // 0) transpose + convert weights -> half [N][K]
    dim3 tb(32, 8);
    transpose_k<<<dim3(QKVC / 32, CC / 32),   tb>>>(w_qkv,  wT + WT_QKV,  CC,   QKVC);
    transpose_k<<<dim3(CC / 32,   CC / 32),   tb>>>(w_proj, wT + WT_PROJ, CC,   CC);
    transpose_k<<<dim3(HIDN / 32, CC / 32),   tb>>>(w1,     wT + WT_W1,   CC,   HIDN);
    transpose_k<<<dim3(CC / 32,   HIDN / 32), tb>>>(w2,     wT + WT_W2,   HIDN, CC);

    // 1) LN1 + roll + window partition -> bufB (half)
    ln_kernel<true><<<TTOT, 96>>>(x, g1, b1, bufB);
    // 2) QKV GEMM -> bufA (half)
    gemm_f16<EPI_BIAS><<<dim3(QKVC / 128, TTOT / 128), 256, GSMEM>>>(
        bufB, wT + WT_QKV, b_qkv, bufA, nullptr, QKVC, CC);
    // 3) tensor-core windowed attention -> bufB (half)
    attn_tc<<<dim3(NHD, BWIN), 128>>>(bufA, rpb, bufB);
    // 4) proj + window reverse + roll + residual(x) -> out (fp32)
    gemm_f16<EPI_PROJ><<<dim3(CC / 128, TTOT / 128), 256, GSMEM>>>(
        bufB, wT + WT_PROJ, b_proj, out, x, CC, CC);
    // 5) LN2 -> bufB (half)
    ln_kernel<false><<<TTOT, 96>>>(out, g2, b2, bufB);
    // 6) FC1 + GELU -> bufA (half)
    gemm_f16<EPI_GELU><<<dim3(HIDN / 128, TTOT / 128), 256, GSMEM>>>(
        bufB, wT + WT_W1, bm1, bufA, nullptr, HIDN, CC);
    // 7) FC2 + residual(out) -> out (fp32)
    gemm_f16<EPI_ADD><<<dim3(CC / 128, TTOT / 128), 256, GSMEM>>>(
        bufA, wT + WT_W2, bm2, out, out, CC, HIDN);
}